// round 9
// baseline (speedup 1.0000x reference)
#include <cuda_runtime.h>
#include <cuda_bf16.h>
#include <cstdint>
#include <cstddef>

#define B_   32
#define T_   512
#define H_   512
#define D_   512
#define SIXH 3072
#define BH   (B_ * H_)

#define NBLK 128
#define CPB  8           // h-columns per block
#define BGRP 16          // batch rows per group
#define NROW 40          // 5 gates * CPB
#define SSTR 520         // bf16 row stride in smem
#define PSTR 44          // partial row stride (floats)
#define NTHR 256

// Scratch (device globals: allocation-free per harness rules)
__device__ float         g_pi[(size_t)B_ * T_ * SIXH];
__device__ __nv_bfloat16 g_hhi[2 * BH];
__device__ __nv_bfloat16 g_hlo[2 * BH];
__device__ unsigned      g_cnt[2][8];
__device__ __nv_bfloat16 g_xhi[(size_t)B_ * T_ * D_];
__device__ __nv_bfloat16 g_xlo[(size_t)B_ * T_ * D_];
__device__ __nv_bfloat16 g_whi[(size_t)SIXH * D_];
__device__ __nv_bfloat16 g_wlo[(size_t)SIXH * D_];

__global__ void init_k() {
    for (int g = 0; g < 2; g++)
        for (int i = 0; i < 8; i++) g_cnt[g][i] = 0u;
}

// ---------------------------------------------------------------------------
__global__ void split_k(const float* __restrict__ src,
                        __nv_bfloat16* __restrict__ hi,
                        __nv_bfloat16* __restrict__ lo, int n4) {
    int i = blockIdx.x * blockDim.x + threadIdx.x;
    if (i >= n4) return;
    float4 f = ((const float4*)src)[i];
    __nv_bfloat16 h0 = __float2bfloat16(f.x);
    __nv_bfloat16 h1 = __float2bfloat16(f.y);
    __nv_bfloat16 h2 = __float2bfloat16(f.z);
    __nv_bfloat16 h3 = __float2bfloat16(f.w);
    __nv_bfloat162 hv0, hv1, lv0, lv1;
    hv0.x = h0; hv0.y = h1; hv1.x = h2; hv1.y = h3;
    lv0.x = __float2bfloat16(f.x - __bfloat162float(h0));
    lv0.y = __float2bfloat16(f.y - __bfloat162float(h1));
    lv1.x = __float2bfloat16(f.z - __bfloat162float(h2));
    lv1.y = __float2bfloat16(f.w - __bfloat162float(h3));
    ((__nv_bfloat162*)hi)[2 * i]     = hv0;
    ((__nv_bfloat162*)hi)[2 * i + 1] = hv1;
    ((__nv_bfloat162*)lo)[2 * i]     = lv0;
    ((__nv_bfloat162*)lo)[2 * i + 1] = lv1;
}

// ---------------------------------------------------------------------------
__device__ __forceinline__ void ldsm_x4(uint32_t& r0, uint32_t& r1,
                                        uint32_t& r2, uint32_t& r3, uint32_t a) {
    asm volatile("ldmatrix.sync.aligned.m8n8.x4.shared.b16 {%0,%1,%2,%3}, [%4];"
                 : "=r"(r0), "=r"(r1), "=r"(r2), "=r"(r3) : "r"(a));
}
__device__ __forceinline__ void ldsm_x2(uint32_t& r0, uint32_t& r1, uint32_t a) {
    asm volatile("ldmatrix.sync.aligned.m8n8.x2.shared.b16 {%0,%1}, [%2];"
                 : "=r"(r0), "=r"(r1) : "r"(a));
}
__device__ __forceinline__ void mma16816(float* c, const uint32_t* a,
                                         uint32_t b0, uint32_t b1) {
    asm volatile(
        "mma.sync.aligned.m16n8k16.row.col.f32.bf16.bf16.f32 "
        "{%0,%1,%2,%3},{%4,%5,%6,%7},{%8,%9},{%0,%1,%2,%3};"
        : "+f"(c[0]), "+f"(c[1]), "+f"(c[2]), "+f"(c[3])
        : "r"(a[0]), "r"(a[1]), "r"(a[2]), "r"(a[3]), "r"(b0), "r"(b1));
}
__device__ __forceinline__ void cpa16(uint32_t dst, const void* src) {
    asm volatile("cp.async.cg.shared.global [%0], [%1], 16;"
                 :: "r"(dst), "l"(src));
}
__device__ __forceinline__ void cpa_commit() {
    asm volatile("cp.async.commit_group;");
}
__device__ __forceinline__ unsigned ldacq(const unsigned* p) {
    unsigned v;
    asm volatile("ld.acquire.gpu.global.u32 %0, [%1];" : "=r"(v) : "l"(p) : "memory");
    return v;
}
__device__ __forceinline__ void red_release(unsigned* p) {
    asm volatile("red.release.gpu.global.add.u32 [%0], 1;" :: "l"(p) : "memory");
}

// ---------------------------------------------------------------------------
// Tensor-core input GEMM (unchanged — known-good 487 us config).
// ---------------------------------------------------------------------------
#define ASTR  48
#define STAGE (4 * 128 * ASTR)

__global__ __launch_bounds__(256, 2) void gemm_pi_mma_k(const float* __restrict__ bi) {
    extern __shared__ char smg[];

    const int tid  = threadIdx.x;
    const int lane = tid & 31;
    const int warp = tid >> 5;
    const int wm   = warp >> 2;
    const int wn   = warp & 3;
    const int m0   = blockIdx.y * 128;
    const int n0   = blockIdx.x * 128;

    const int lrow  = tid >> 1;
    const int lhalf = tid & 1;
    const __nv_bfloat16* pxh = g_xhi + (size_t)(m0 + lrow) * D_ + lhalf * 8;
    const __nv_bfloat16* pxl = g_xlo + (size_t)(m0 + lrow) * D_ + lhalf * 8;
    const __nv_bfloat16* pwh = g_whi + (size_t)(n0 + lrow) * D_ + lhalf * 8;
    const __nv_bfloat16* pwl = g_wlo + (size_t)(n0 + lrow) * D_ + lhalf * 8;

    const uint32_t sbase = (uint32_t)__cvta_generic_to_shared(smg);
    const uint32_t stoff = lrow * ASTR + lhalf * 16;

    const int rowA = wm * 64 + (lane & 15);
    const uint32_t aAh0 = sbase + rowA * ASTR + (lane >> 4) * 16;
    const uint32_t aAl0 = aAh0 + 128 * ASTR;
    const int rowB = wn * 32 + (lane & 7) + ((lane >> 4) << 3);
    const uint32_t aBh0 = sbase + 2 * 128 * ASTR + rowB * ASTR + ((lane >> 3) & 1) * 16;
    const uint32_t aBl0 = aBh0 + 128 * ASTR;

    float acc[4][4][4];
#pragma unroll
    for (int i = 0; i < 4; i++)
#pragma unroll
        for (int j = 0; j < 4; j++)
#pragma unroll
            for (int e = 0; e < 4; e++) acc[i][j][e] = 0.f;

    auto commit_stage = [&](int p, int kts) {
        uint32_t d = sbase + p * STAGE + stoff;
        const int ko = kts * 16;
        cpa16(d,                  pxh + ko);
        cpa16(d + 128 * ASTR,     pxl + ko);
        cpa16(d + 2 * 128 * ASTR, pwh + ko);
        cpa16(d + 3 * 128 * ASTR, pwl + ko);
        cpa_commit();
    };

    commit_stage(0, 0);
    commit_stage(1, 1);

    for (int kts = 0; kts < 32; kts++) {
        if (kts < 31) asm volatile("cp.async.wait_group 1;");
        else          asm volatile("cp.async.wait_group 0;");
        __syncthreads();
        if (kts + 2 < 32) commit_stage((kts + 2) % 3, kts + 2);

        const uint32_t po = (kts % 3) * STAGE;

        uint32_t ah[4][4], al[4][4], bh[4][2], bl[4][2];
#pragma unroll
        for (int mi = 0; mi < 4; mi++) {
            ldsm_x4(ah[mi][0], ah[mi][1], ah[mi][2], ah[mi][3], aAh0 + po + mi * 16 * ASTR);
            ldsm_x4(al[mi][0], al[mi][1], al[mi][2], al[mi][3], aAl0 + po + mi * 16 * ASTR);
        }
#pragma unroll
        for (int bg = 0; bg < 2; bg++) {
            ldsm_x4(bh[2 * bg][0], bh[2 * bg][1], bh[2 * bg + 1][0], bh[2 * bg + 1][1],
                    aBh0 + po + bg * 16 * ASTR);
            ldsm_x4(bl[2 * bg][0], bl[2 * bg][1], bl[2 * bg + 1][0], bl[2 * bg + 1][1],
                    aBl0 + po + bg * 16 * ASTR);
        }
#pragma unroll
        for (int mi = 0; mi < 4; mi++)
#pragma unroll
            for (int ni = 0; ni < 4; ni++) {
                mma16816(acc[mi][ni], ah[mi], bh[ni][0], bh[ni][1]);
                mma16816(acc[mi][ni], ah[mi], bl[ni][0], bl[ni][1]);
                mma16816(acc[mi][ni], al[mi], bh[ni][0], bh[ni][1]);
            }
    }

#pragma unroll
    for (int ni = 0; ni < 4; ni++) {
        const int n = n0 + wn * 32 + ni * 8 + 2 * (lane & 3);
        float b0 = bi[n], b1 = bi[n + 1];
#pragma unroll
        for (int mi = 0; mi < 4; mi++) {
            const int m = m0 + wm * 64 + mi * 16 + (lane >> 2);
            float* C0 = g_pi + (size_t)m * SIXH + n;
            float* C1 = g_pi + (size_t)(m + 8) * SIXH + n;
            *(float2*)C0 = make_float2(acc[mi][ni][0] + b0, acc[mi][ni][1] + b1);
            *(float2*)C1 = make_float2(acc[mi][ni][2] + b0, acc[mi][ni][3] + b1);
        }
    }
}

// ---------------------------------------------------------------------------
// Persistent scan: cp.async-staged A (R6 path) + register-resident B frags +
// release/acquire dataflow sync.
// ---------------------------------------------------------------------------
__device__ __forceinline__ float sigm(float x)  { return 1.f / (1.f + __expf(-x)); }
__device__ __forceinline__ float tanh_(float x) { return 1.f - 2.f / (__expf(2.f * x) + 1.f); }

__global__ __launch_bounds__(NTHR, 1) void lstm_scan_k(
    const float* __restrict__ Ws, const float* __restrict__ bs,
    const int* __restrict__ lengths, float* __restrict__ out)
{
    extern __shared__ char smc[];
    __nv_bfloat16* sAh   = (__nv_bfloat16*)smc;          // 16 x SSTR
    __nv_bfloat16* sAl   = sAh + 16 * SSTR;              // 16 x SSTR
    __nv_bfloat16* sWh   = sAl + 16 * SSTR;              // NROW x SSTR
    __nv_bfloat16* sWl   = sWh + NROW * SSTR;            // NROW x SSTR
    float*         sPart = (float*)(sWl + NROW * SSTR);  // 8 x 16 x PSTR

    const int tid   = threadIdx.x;
    const int blk   = blockIdx.x;
    const int lane  = tid & 31;
    const int warp  = tid >> 5;
    const int group = blk >> 6;
    const int cb    = blk & 63;
    const int sub   = cb >> 3;
    const int kh    = warp;

    // --- Ws -> smem bf16 split ---
    for (int i = tid; i < NROW * (H_ / 8); i += NTHR) {
        int l  = i >> 6;
        int d8 = (i & 63) << 3;
        __nv_bfloat16* ph = sWh + l * SSTR + d8;
        __nv_bfloat16* pl = sWl + l * SSTR + d8;
        int row = (l >> 3) * H_ + cb * CPB + (l & 7);
        const float* p = Ws + (size_t)row * H_ + d8;
#pragma unroll
        for (int q = 0; q < 8; q++) {
            float f = p[q];
            __nv_bfloat16 hh = __float2bfloat16(f);
            ph[q] = hh;
            pl[q] = __float2bfloat16(f - __bfloat162float(hh));
        }
    }
    __syncthreads();

    // --- Hoist ALL B fragments into registers (Ws immutable, 80 regs) ---
    const uint32_t aBh = (uint32_t)__cvta_generic_to_shared(
        sWh + (size_t)(lane & 7) * SSTR) + ((lane >> 3) & 1) * 16 + kh * 128;
    const uint32_t aBl = aBh + NROW * SSTR * 2;
    uint32_t Bh[4][5][2], Bl[4][5][2];
#pragma unroll
    for (int kk = 0; kk < 4; kk++)
#pragma unroll
        for (int ni = 0; ni < 5; ni++) {
            const uint32_t off = kk * 32 + ni * 8 * SSTR * 2;
            ldsm_x2(Bh[kk][ni][0], Bh[kk][ni][1], aBh + off);
            ldsm_x2(Bl[kk][ni][0], Bl[kk][ni][1], aBl + off);
        }

    // ldmatrix A source addresses (staged chunk)
    const uint32_t aAh = (uint32_t)__cvta_generic_to_shared(
        sAh + (size_t)(lane & 15) * SSTR) + (lane >> 4) * 16 + kh * 128;
    const uint32_t aAl = aAh + 16 * SSTR * 2;

    // Gate threads: tid<128 owns (b_local = tid>>3, jj = tid&7)
    float c_reg = 0.f, h_reg = 0.f;
    float bsv[5] = {0.f, 0.f, 0.f, 0.f, 0.f};
    int bg = 0, j0 = 0, len = 0, b_local = 0;
    if (tid < 128) {
        b_local = tid >> 3;
        bg = group * BGRP + b_local;
        j0 = cb * CPB + (tid & 7);
        len = lengths[bg];
#pragma unroll
        for (int g = 0; g < 5; g++) bsv[g] = bs[g * H_ + j0];
        __stcg((unsigned short*)&g_hhi[bg * H_ + j0], (unsigned short)0);
        __stcg((unsigned short*)&g_hlo[bg * H_ + j0], (unsigned short)0);
    }
    __syncthreads();
    if (tid == 0) red_release(&g_cnt[group][sub]);   // h0 published

    const int hbase = group * BGRP * H_;
    const unsigned* cptr = &g_cnt[group][kh];
    const uint32_t dh = (uint32_t)__cvta_generic_to_shared(sAh);
    const uint32_t dl = (uint32_t)__cvta_generic_to_shared(sAl);

    // Deep pi prefetch
    float pv_cur[6] = {0,0,0,0,0,0}, pv_nxt[6] = {0,0,0,0,0,0};
    const float* ppi = (tid < 128) ? g_pi + (size_t)bg * T_ * SIXH + j0 : g_pi;
    if (tid < 128) {
#pragma unroll
        for (int g = 0; g < 6; g++) pv_cur[g] = __ldg(ppi + g * H_);
    }

    for (int t = 0; t < T_; t++) {
        if (tid < 128 && t + 1 < T_) {
            const float* pp = ppi + (size_t)(t + 1) * SIXH;
#pragma unroll
            for (int g = 0; g < 6; g++) pv_nxt[g] = __ldg(pp + g * H_);
        }

        // poll this chunk's writers (acquire)
        if (lane == 0) {
            while (ldacq(cptr) < 8u * (unsigned)(t + 1)) {}
        }
        __syncwarp();

        // warp-local coalesced copy of chunk kh: 16 rows x 64 cols, hi+lo
        {
            const char* ph = (const char*)(g_hhi + (t & 1) * BH + hbase);
            const char* pl = (const char*)(g_hlo + (t & 1) * BH + hbase);
#pragma unroll
            for (int i = lane; i < 128; i += 32) {
                int r  = i >> 3;
                int cc = ((i & 7) << 3) + kh * 64;
                cpa16(dh + (r * SSTR + cc) * 2, ph + (r * H_ + cc) * 2);
                cpa16(dl + (r * SSTR + cc) * 2, pl + (r * H_ + cc) * 2);
            }
            cpa_commit();
            asm volatile("cp.async.wait_group 0;");
            __syncwarp();
        }

        // MMA: 16x40 partial over k-chunk [kh*64, kh*64+64)
        float acc[5][4];
#pragma unroll
        for (int ni = 0; ni < 5; ni++)
#pragma unroll
            for (int e = 0; e < 4; e++) acc[ni][e] = 0.f;
#pragma unroll
        for (int kk = 0; kk < 4; kk++) {
            const uint32_t ko = kk * 32;
            uint32_t Ah[4], Al[4];
            ldsm_x4(Ah[0], Ah[1], Ah[2], Ah[3], aAh + ko);
            ldsm_x4(Al[0], Al[1], Al[2], Al[3], aAl + ko);
#pragma unroll
            for (int ni = 0; ni < 5; ni++) {
                mma16816(acc[ni], Ah, Bh[kk][ni][0], Bh[kk][ni][1]);
                mma16816(acc[ni], Al, Bh[kk][ni][0], Bh[kk][ni][1]);
                mma16816(acc[ni], Ah, Bl[kk][ni][0], Bl[kk][ni][1]);
            }
        }

        {
            float* pp = sPart + kh * 16 * PSTR;
            const int r = lane >> 2;
#pragma unroll
            for (int ni = 0; ni < 5; ni++) {
                const int n = ni * 8 + 2 * (lane & 3);
                *(float2*)&pp[r * PSTR + n]       = make_float2(acc[ni][0], acc[ni][1]);
                *(float2*)&pp[(r + 8) * PSTR + n] = make_float2(acc[ni][2], acc[ni][3]);
            }
        }
        __syncthreads();   // partials ready

        // Gate phase
        if (tid < 128) {
            const int jj = tid & 7;
            float ps[5];
#pragma unroll
            for (int g = 0; g < 5; g++) {
                float s = 0.f;
#pragma unroll
                for (int w = 0; w < 8; w++)
                    s += sPart[w * 16 * PSTR + b_local * PSTR + g * 8 + jj];
                ps[g] = s + bsv[g];
            }
            float iv = sigm(pv_cur[0] + ps[0]);
            float fv = sigm(pv_cur[1] + ps[1]);
            float gv = tanh_(pv_cur[2] + ps[2]);
            float ov = sigm(pv_cur[3] + ps[3]);
            float cn = iv * gv + fv * c_reg;
            float o1 = ov * tanh_(cn);
            float rv = sigm(pv_cur[4] + ps[4]);
            float o2 = rv * o1 + (1.f - rv) * pv_cur[5];
            bool  m  = (t < len);
            h_reg = m ? o2 : h_reg;
            c_reg = m ? cn : c_reg;
            __nv_bfloat16 hh = __float2bfloat16(h_reg);
            __nv_bfloat16 hl = __float2bfloat16(h_reg - __bfloat162float(hh));
            const int idx = ((t + 1) & 1) * BH + bg * H_ + j0;
            __stcg((unsigned short*)&g_hhi[idx], __bfloat16_as_ushort(hh));
            __stcg((unsigned short*)&g_hlo[idx], __bfloat16_as_ushort(hl));
            out[((size_t)bg * T_ + t) * H_ + j0] = m ? o2 : 0.f;
            if (t == T_ - 1) {
                out[(size_t)B_ * T_ * H_ + bg * H_ + j0]      = h_reg;
                out[(size_t)B_ * T_ * H_ + BH + bg * H_ + j0] = c_reg;
            }
        }
#pragma unroll
        for (int g = 0; g < 6; g++) pv_cur[g] = pv_nxt[g];

        __syncthreads();   // h stores ordered before release
        if (tid == 0) red_release(&g_cnt[group][sub]);
    }
}

// ---------------------------------------------------------------------------
extern "C" void kernel_launch(void* const* d_in, const int* in_sizes, int n_in,
                              void* d_out, int out_size) {
    const float* x       = (const float*)d_in[0];
    const int*   lengths = (const int*)  d_in[1];
    const float* Wi      = (const float*)d_in[2];
    const float* bi      = (const float*)d_in[3];
    const float* Ws      = (const float*)d_in[4];
    const float* bs      = (const float*)d_in[5];
    float* out = (float*)d_out;

    const int smem_scan = (16 + 16 + NROW + NROW) * SSTR * 2 + 8 * 16 * PSTR * 4; // 139,008 B
    const int smem_gemm = 3 * STAGE;
    cudaFuncSetAttribute(lstm_scan_k,   cudaFuncAttributeMaxDynamicSharedMemorySize, smem_scan);
    cudaFuncSetAttribute(gemm_pi_mma_k, cudaFuncAttributeMaxDynamicSharedMemorySize, smem_gemm);

    init_k<<<1, 1>>>();

    __nv_bfloat16 *xhi, *xlo, *whi, *wlo;
    cudaGetSymbolAddress((void**)&xhi, g_xhi);
    cudaGetSymbolAddress((void**)&xlo, g_xlo);
    cudaGetSymbolAddress((void**)&whi, g_whi);
    cudaGetSymbolAddress((void**)&wlo, g_wlo);

    int nx4 = (B_ * T_ * D_) / 4;
    int nw4 = (SIXH * D_) / 4;
    split_k<<<(nx4 + 255) / 256, 256>>>(x, xhi, xlo, nx4);
    split_k<<<(nw4 + 255) / 256, 256>>>(Wi, whi, wlo, nw4);

    gemm_pi_mma_k<<<dim3(SIXH / 128, (B_ * T_) / 128), 256, smem_gemm>>>(bi);
    lstm_scan_k<<<NBLK, NTHR, smem_scan>>>(Ws, bs, lengths, out);
}

// round 10
// speedup vs baseline: 1.0417x; 1.0417x over previous
#include <cuda_runtime.h>
#include <cuda_bf16.h>
#include <cstdint>
#include <cstddef>

#define B_   32
#define T_   512
#define H_   512
#define D_   512
#define SIXH 3072
#define BH   (B_ * H_)

#define NBLK 128
#define CPB  8           // h-columns per block
#define BGRP 16          // batch rows per group
#define NROW 40          // 5 gates * CPB
#define SSTR 520         // bf16 row stride in smem
#define PSTR 44          // partial row stride (floats)
#define NTHR 256

// Scratch (device globals: allocation-free per harness rules)
__device__ float         g_pi[(size_t)B_ * T_ * SIXH];
__device__ __nv_bfloat16 g_hhi[2 * BH];
__device__ __nv_bfloat16 g_hlo[2 * BH];
__device__ unsigned      g_cnt[2][8];
__device__ __nv_bfloat16 g_xhi[(size_t)B_ * T_ * D_];
__device__ __nv_bfloat16 g_xlo[(size_t)B_ * T_ * D_];
__device__ __nv_bfloat16 g_whi[(size_t)SIXH * D_];
__device__ __nv_bfloat16 g_wlo[(size_t)SIXH * D_];

__global__ void init_k() {
    for (int g = 0; g < 2; g++)
        for (int i = 0; i < 8; i++) g_cnt[g][i] = 0u;
}

// ---------------------------------------------------------------------------
__global__ void split_k(const float* __restrict__ src,
                        __nv_bfloat16* __restrict__ hi,
                        __nv_bfloat16* __restrict__ lo, int n4) {
    int i = blockIdx.x * blockDim.x + threadIdx.x;
    if (i >= n4) return;
    float4 f = ((const float4*)src)[i];
    __nv_bfloat16 h0 = __float2bfloat16(f.x);
    __nv_bfloat16 h1 = __float2bfloat16(f.y);
    __nv_bfloat16 h2 = __float2bfloat16(f.z);
    __nv_bfloat16 h3 = __float2bfloat16(f.w);
    __nv_bfloat162 hv0, hv1, lv0, lv1;
    hv0.x = h0; hv0.y = h1; hv1.x = h2; hv1.y = h3;
    lv0.x = __float2bfloat16(f.x - __bfloat162float(h0));
    lv0.y = __float2bfloat16(f.y - __bfloat162float(h1));
    lv1.x = __float2bfloat16(f.z - __bfloat162float(h2));
    lv1.y = __float2bfloat16(f.w - __bfloat162float(h3));
    ((__nv_bfloat162*)hi)[2 * i]     = hv0;
    ((__nv_bfloat162*)hi)[2 * i + 1] = hv1;
    ((__nv_bfloat162*)lo)[2 * i]     = lv0;
    ((__nv_bfloat162*)lo)[2 * i + 1] = lv1;
}

// ---------------------------------------------------------------------------
__device__ __forceinline__ void ldsm_x4(uint32_t& r0, uint32_t& r1,
                                        uint32_t& r2, uint32_t& r3, uint32_t a) {
    asm volatile("ldmatrix.sync.aligned.m8n8.x4.shared.b16 {%0,%1,%2,%3}, [%4];"
                 : "=r"(r0), "=r"(r1), "=r"(r2), "=r"(r3) : "r"(a));
}
__device__ __forceinline__ void ldsm_x2(uint32_t& r0, uint32_t& r1, uint32_t a) {
    asm volatile("ldmatrix.sync.aligned.m8n8.x2.shared.b16 {%0,%1}, [%2];"
                 : "=r"(r0), "=r"(r1) : "r"(a));
}
__device__ __forceinline__ void mma16816(float* c, const uint32_t* a,
                                         uint32_t b0, uint32_t b1) {
    asm volatile(
        "mma.sync.aligned.m16n8k16.row.col.f32.bf16.bf16.f32 "
        "{%0,%1,%2,%3},{%4,%5,%6,%7},{%8,%9},{%0,%1,%2,%3};"
        : "+f"(c[0]), "+f"(c[1]), "+f"(c[2]), "+f"(c[3])
        : "r"(a[0]), "r"(a[1]), "r"(a[2]), "r"(a[3]), "r"(b0), "r"(b1));
}
__device__ __forceinline__ void cpa16(uint32_t dst, const void* src) {
    asm volatile("cp.async.cg.shared.global [%0], [%1], 16;"
                 :: "r"(dst), "l"(src));
}
__device__ __forceinline__ void cpa_commit() {
    asm volatile("cp.async.commit_group;");
}
__device__ __forceinline__ unsigned ldacq(const unsigned* p) {
    unsigned v;
    asm volatile("ld.acquire.gpu.global.u32 %0, [%1];" : "=r"(v) : "l"(p) : "memory");
    return v;
}
__device__ __forceinline__ void red_release(unsigned* p) {
    asm volatile("red.release.gpu.global.add.u32 [%0], 1;" :: "l"(p) : "memory");
}

// ---------------------------------------------------------------------------
// Tensor-core input GEMM (unchanged — known-good 487 us config).
// ---------------------------------------------------------------------------
#define ASTR  48
#define STAGE (4 * 128 * ASTR)

__global__ __launch_bounds__(256, 2) void gemm_pi_mma_k(const float* __restrict__ bi) {
    extern __shared__ char smg[];

    const int tid  = threadIdx.x;
    const int lane = tid & 31;
    const int warp = tid >> 5;
    const int wm   = warp >> 2;
    const int wn   = warp & 3;
    const int m0   = blockIdx.y * 128;
    const int n0   = blockIdx.x * 128;

    const int lrow  = tid >> 1;
    const int lhalf = tid & 1;
    const __nv_bfloat16* pxh = g_xhi + (size_t)(m0 + lrow) * D_ + lhalf * 8;
    const __nv_bfloat16* pxl = g_xlo + (size_t)(m0 + lrow) * D_ + lhalf * 8;
    const __nv_bfloat16* pwh = g_whi + (size_t)(n0 + lrow) * D_ + lhalf * 8;
    const __nv_bfloat16* pwl = g_wlo + (size_t)(n0 + lrow) * D_ + lhalf * 8;

    const uint32_t sbase = (uint32_t)__cvta_generic_to_shared(smg);
    const uint32_t stoff = lrow * ASTR + lhalf * 16;

    const int rowA = wm * 64 + (lane & 15);
    const uint32_t aAh0 = sbase + rowA * ASTR + (lane >> 4) * 16;
    const uint32_t aAl0 = aAh0 + 128 * ASTR;
    const int rowB = wn * 32 + (lane & 7) + ((lane >> 4) << 3);
    const uint32_t aBh0 = sbase + 2 * 128 * ASTR + rowB * ASTR + ((lane >> 3) & 1) * 16;
    const uint32_t aBl0 = aBh0 + 128 * ASTR;

    float acc[4][4][4];
#pragma unroll
    for (int i = 0; i < 4; i++)
#pragma unroll
        for (int j = 0; j < 4; j++)
#pragma unroll
            for (int e = 0; e < 4; e++) acc[i][j][e] = 0.f;

    auto commit_stage = [&](int p, int kts) {
        uint32_t d = sbase + p * STAGE + stoff;
        const int ko = kts * 16;
        cpa16(d,                  pxh + ko);
        cpa16(d + 128 * ASTR,     pxl + ko);
        cpa16(d + 2 * 128 * ASTR, pwh + ko);
        cpa16(d + 3 * 128 * ASTR, pwl + ko);
        cpa_commit();
    };

    commit_stage(0, 0);
    commit_stage(1, 1);

    for (int kts = 0; kts < 32; kts++) {
        if (kts < 31) asm volatile("cp.async.wait_group 1;");
        else          asm volatile("cp.async.wait_group 0;");
        __syncthreads();
        if (kts + 2 < 32) commit_stage((kts + 2) % 3, kts + 2);

        const uint32_t po = (kts % 3) * STAGE;

        uint32_t ah[4][4], al[4][4], bh[4][2], bl[4][2];
#pragma unroll
        for (int mi = 0; mi < 4; mi++) {
            ldsm_x4(ah[mi][0], ah[mi][1], ah[mi][2], ah[mi][3], aAh0 + po + mi * 16 * ASTR);
            ldsm_x4(al[mi][0], al[mi][1], al[mi][2], al[mi][3], aAl0 + po + mi * 16 * ASTR);
        }
#pragma unroll
        for (int bg = 0; bg < 2; bg++) {
            ldsm_x4(bh[2 * bg][0], bh[2 * bg][1], bh[2 * bg + 1][0], bh[2 * bg + 1][1],
                    aBh0 + po + bg * 16 * ASTR);
            ldsm_x4(bl[2 * bg][0], bl[2 * bg][1], bl[2 * bg + 1][0], bl[2 * bg + 1][1],
                    aBl0 + po + bg * 16 * ASTR);
        }
#pragma unroll
        for (int mi = 0; mi < 4; mi++)
#pragma unroll
            for (int ni = 0; ni < 4; ni++) {
                mma16816(acc[mi][ni], ah[mi], bh[ni][0], bh[ni][1]);
                mma16816(acc[mi][ni], ah[mi], bl[ni][0], bl[ni][1]);
                mma16816(acc[mi][ni], al[mi], bh[ni][0], bh[ni][1]);
            }
    }

#pragma unroll
    for (int ni = 0; ni < 4; ni++) {
        const int n = n0 + wn * 32 + ni * 8 + 2 * (lane & 3);
        float b0 = bi[n], b1 = bi[n + 1];
#pragma unroll
        for (int mi = 0; mi < 4; mi++) {
            const int m = m0 + wm * 64 + mi * 16 + (lane >> 2);
            float* C0 = g_pi + (size_t)m * SIXH + n;
            float* C1 = g_pi + (size_t)(m + 8) * SIXH + n;
            *(float2*)C0 = make_float2(acc[mi][ni][0] + b0, acc[mi][ni][1] + b1);
            *(float2*)C1 = make_float2(acc[mi][ni][2] + b0, acc[mi][ni][3] + b1);
        }
    }
}

// ---------------------------------------------------------------------------
// Persistent scan — EXACT R6 structure (per-step ldsm for A and B; low reg
// pressure), single delta: release/acquire dataflow sync instead of
// threadfence + plain atomic + volatile poll.
// ---------------------------------------------------------------------------
__device__ __forceinline__ float sigm(float x)  { return 1.f / (1.f + __expf(-x)); }
__device__ __forceinline__ float tanh_(float x) { return 1.f - 2.f / (__expf(2.f * x) + 1.f); }

__global__ __launch_bounds__(NTHR, 1) void lstm_scan_k(
    const float* __restrict__ Ws, const float* __restrict__ bs,
    const int* __restrict__ lengths, float* __restrict__ out)
{
    extern __shared__ char smc[];
    __nv_bfloat16* sAh   = (__nv_bfloat16*)smc;          // 16 x SSTR
    __nv_bfloat16* sAl   = sAh + 16 * SSTR;              // 16 x SSTR
    __nv_bfloat16* sWh   = sAl + 16 * SSTR;              // NROW x SSTR
    __nv_bfloat16* sWl   = sWh + NROW * SSTR;            // NROW x SSTR
    float*         sPart = (float*)(sWl + NROW * SSTR);  // 8 x 16 x PSTR

    const int tid   = threadIdx.x;
    const int blk   = blockIdx.x;
    const int lane  = tid & 31;
    const int warp  = tid >> 5;
    const int group = blk >> 6;
    const int cb    = blk & 63;
    const int sub   = cb >> 3;
    const int kh    = warp;           // k-chunk owned by this warp

    // --- Ws -> smem bf16 split ---
    for (int i = tid; i < NROW * (H_ / 8); i += NTHR) {
        int l  = i >> 6;
        int d8 = (i & 63) << 3;
        __nv_bfloat16* ph = sWh + l * SSTR + d8;
        __nv_bfloat16* pl = sWl + l * SSTR + d8;
        int row = (l >> 3) * H_ + cb * CPB + (l & 7);
        const float* p = Ws + (size_t)row * H_ + d8;
#pragma unroll
        for (int q = 0; q < 8; q++) {
            float f = p[q];
            __nv_bfloat16 hh = __float2bfloat16(f);
            ph[q] = hh;
            pl[q] = __float2bfloat16(f - __bfloat162float(hh));
        }
    }

    // MMA addressing: warp = k-chunk kh (64 k-elems each)
    const uint32_t aAh = (uint32_t)__cvta_generic_to_shared(
        sAh + (size_t)(lane & 15) * SSTR) + (lane >> 4) * 16 + kh * 128;
    const uint32_t aAl = aAh + 16 * SSTR * 2;
    const uint32_t aBh = (uint32_t)__cvta_generic_to_shared(
        sWh + (size_t)(lane & 7) * SSTR) + ((lane >> 3) & 1) * 16 + kh * 128;
    const uint32_t aBl = aBh + NROW * SSTR * 2;

    // Gate threads: tid<128 owns (b_local = tid>>3, jj = tid&7)
    float c_reg = 0.f, h_reg = 0.f;
    float bsv[5] = {0.f, 0.f, 0.f, 0.f, 0.f};
    int bg = 0, j0 = 0, len = 0, b_local = 0;
    if (tid < 128) {
        b_local = tid >> 3;
        bg = group * BGRP + b_local;
        j0 = cb * CPB + (tid & 7);
        len = lengths[bg];
#pragma unroll
        for (int g = 0; g < 5; g++) bsv[g] = bs[g * H_ + j0];
        __stcg((unsigned short*)&g_hhi[bg * H_ + j0], (unsigned short)0);
        __stcg((unsigned short*)&g_hlo[bg * H_ + j0], (unsigned short)0);
    }
    __syncthreads();
    if (tid == 0) red_release(&g_cnt[group][sub]);   // h0 published (release)

    const int hbase = group * BGRP * H_;
    const unsigned* cptr = &g_cnt[group][kh];
    const uint32_t dh = (uint32_t)__cvta_generic_to_shared(sAh);
    const uint32_t dl = (uint32_t)__cvta_generic_to_shared(sAl);

    // Deep pi prefetch
    float pv_cur[6] = {0,0,0,0,0,0}, pv_nxt[6] = {0,0,0,0,0,0};
    const float* ppi = (tid < 128) ? g_pi + (size_t)bg * T_ * SIXH + j0 : g_pi;
    if (tid < 128) {
#pragma unroll
        for (int g = 0; g < 6; g++) pv_cur[g] = __ldg(ppi + g * H_);
    }

    for (int t = 0; t < T_; t++) {
        if (tid < 128 && t + 1 < T_) {
            const float* pp = ppi + (size_t)(t + 1) * SIXH;
#pragma unroll
            for (int g = 0; g < 6; g++) pv_nxt[g] = __ldg(pp + g * H_);
        }

        // poll this chunk's writers (acquire)
        if (lane == 0) {
            while (ldacq(cptr) < 8u * (unsigned)(t + 1)) {}
        }
        __syncwarp();

        // warp-local coalesced copy of chunk kh: 16 rows x 64 cols, hi+lo
        {
            const char* ph = (const char*)(g_hhi + (t & 1) * BH + hbase);
            const char* pl = (const char*)(g_hlo + (t & 1) * BH + hbase);
#pragma unroll
            for (int i = lane; i < 128; i += 32) {
                int r  = i >> 3;
                int cc = ((i & 7) << 3) + kh * 64;
                cpa16(dh + (r * SSTR + cc) * 2, ph + (r * H_ + cc) * 2);
                cpa16(dl + (r * SSTR + cc) * 2, pl + (r * H_ + cc) * 2);
            }
            cpa_commit();
            asm volatile("cp.async.wait_group 0;");
            __syncwarp();
        }

        // MMA: 16x40 partial over k-chunk [kh*64, kh*64+64)
        float acc[5][4];
#pragma unroll
        for (int ni = 0; ni < 5; ni++)
#pragma unroll
            for (int e = 0; e < 4; e++) acc[ni][e] = 0.f;
#pragma unroll
        for (int kk = 0; kk < 4; kk++) {
            const uint32_t ko = kk * 32;
            uint32_t Ah[4], Al[4];
            ldsm_x4(Ah[0], Ah[1], Ah[2], Ah[3], aAh + ko);
            ldsm_x4(Al[0], Al[1], Al[2], Al[3], aAl + ko);
#pragma unroll
            for (int ni = 0; ni < 5; ni++) {
                const uint32_t bo = ko + ni * 8 * SSTR * 2;
                uint32_t b0h, b1h, b0l, b1l;
                ldsm_x2(b0h, b1h, aBh + bo);
                ldsm_x2(b0l, b1l, aBl + bo);
                mma16816(acc[ni], Ah, b0h, b1h);
                mma16816(acc[ni], Al, b0h, b1h);
                mma16816(acc[ni], Ah, b0l, b1l);
            }
        }

        {
            float* pp = sPart + kh * 16 * PSTR;
            const int r = lane >> 2;
#pragma unroll
            for (int ni = 0; ni < 5; ni++) {
                const int n = ni * 8 + 2 * (lane & 3);
                *(float2*)&pp[r * PSTR + n]       = make_float2(acc[ni][0], acc[ni][1]);
                *(float2*)&pp[(r + 8) * PSTR + n] = make_float2(acc[ni][2], acc[ni][3]);
            }
        }
        __syncthreads();   // partials ready

        // Gate phase
        if (tid < 128) {
            const int jj = tid & 7;
            float ps[5];
#pragma unroll
            for (int g = 0; g < 5; g++) {
                float s = 0.f;
#pragma unroll
                for (int w = 0; w < 8; w++)
                    s += sPart[w * 16 * PSTR + b_local * PSTR + g * 8 + jj];
                ps[g] = s + bsv[g];
            }
            float iv = sigm(pv_cur[0] + ps[0]);
            float fv = sigm(pv_cur[1] + ps[1]);
            float gv = tanh_(pv_cur[2] + ps[2]);
            float ov = sigm(pv_cur[3] + ps[3]);
            float cn = iv * gv + fv * c_reg;
            float o1 = ov * tanh_(cn);
            float rv = sigm(pv_cur[4] + ps[4]);
            float o2 = rv * o1 + (1.f - rv) * pv_cur[5];
            bool  m  = (t < len);
            h_reg = m ? o2 : h_reg;
            c_reg = m ? cn : c_reg;
            __nv_bfloat16 hh = __float2bfloat16(h_reg);
            __nv_bfloat16 hl = __float2bfloat16(h_reg - __bfloat162float(hh));
            const int idx = ((t + 1) & 1) * BH + bg * H_ + j0;
            __stcg((unsigned short*)&g_hhi[idx], __bfloat16_as_ushort(hh));
            __stcg((unsigned short*)&g_hlo[idx], __bfloat16_as_ushort(hl));
            out[((size_t)bg * T_ + t) * H_ + j0] = m ? o2 : 0.f;
            if (t == T_ - 1) {
                out[(size_t)B_ * T_ * H_ + bg * H_ + j0]      = h_reg;
                out[(size_t)B_ * T_ * H_ + BH + bg * H_ + j0] = c_reg;
            }
        }
#pragma unroll
        for (int g = 0; g < 6; g++) pv_cur[g] = pv_nxt[g];

        __syncthreads();   // h stores ordered before the release (CG grid-sync pattern)
        if (tid == 0) red_release(&g_cnt[group][sub]);
    }
}

// ---------------------------------------------------------------------------
extern "C" void kernel_launch(void* const* d_in, const int* in_sizes, int n_in,
                              void* d_out, int out_size) {
    const float* x       = (const float*)d_in[0];
    const int*   lengths = (const int*)  d_in[1];
    const float* Wi      = (const float*)d_in[2];
    const float* bi      = (const float*)d_in[3];
    const float* Ws      = (const float*)d_in[4];
    const float* bs      = (const float*)d_in[5];
    float* out = (float*)d_out;

    const int smem_scan = (16 + 16 + NROW + NROW) * SSTR * 2 + 8 * 16 * PSTR * 4; // 139,008 B
    const int smem_gemm = 3 * STAGE;
    cudaFuncSetAttribute(lstm_scan_k,   cudaFuncAttributeMaxDynamicSharedMemorySize, smem_scan);
    cudaFuncSetAttribute(gemm_pi_mma_k, cudaFuncAttributeMaxDynamicSharedMemorySize, smem_gemm);

    init_k<<<1, 1>>>();

    __nv_bfloat16 *xhi, *xlo, *whi, *wlo;
    cudaGetSymbolAddress((void**)&xhi, g_xhi);
    cudaGetSymbolAddress((void**)&xlo, g_xlo);
    cudaGetSymbolAddress((void**)&whi, g_whi);
    cudaGetSymbolAddress((void**)&wlo, g_wlo);

    int nx4 = (B_ * T_ * D_) / 4;
    int nw4 = (SIXH * D_) / 4;
    split_k<<<(nx4 + 255) / 256, 256>>>(x, xhi, xlo, nx4);
    split_k<<<(nw4 + 255) / 256, 256>>>(Wi, whi, wlo, nw4);

    gemm_pi_mma_k<<<dim3(SIXH / 128, (B_ * T_) / 128), 256, smem_gemm>>>(bi);
    lstm_scan_k<<<NBLK, NTHR, smem_scan>>>(Ws, bs, lengths, out);
}

// round 11
// speedup vs baseline: 1.1223x; 1.0774x over previous
#include <cuda_runtime.h>
#include <cuda_bf16.h>
#include <cstdint>
#include <cstddef>

#define B_   32
#define T_   512
#define H_   512
#define D_   512
#define SIXH 3072
#define BH   (B_ * H_)

#define NBLK 128
#define CPB  8           // h-columns per block
#define BGRP 16          // batch rows per group
#define NROW 40          // 5 gates * CPB
#define SSTR 520         // bf16 row stride in smem
#define PSTR 44          // partial row stride (floats)
#define NTHR 256

// Scratch (device globals: allocation-free per harness rules)
__device__ float         g_pi[(size_t)B_ * T_ * SIXH];
__device__ __nv_bfloat16 g_hhi[2 * BH];
__device__ __nv_bfloat16 g_hlo[2 * BH];
__device__ unsigned      g_cnt[2][8];
__device__ __nv_bfloat16 g_xhi[(size_t)B_ * T_ * D_];
__device__ __nv_bfloat16 g_xlo[(size_t)B_ * T_ * D_];
__device__ __nv_bfloat16 g_whi[(size_t)SIXH * D_];
__device__ __nv_bfloat16 g_wlo[(size_t)SIXH * D_];

__global__ void init_k() {
    for (int g = 0; g < 2; g++)
        for (int i = 0; i < 8; i++) g_cnt[g][i] = 0u;
}

// ---------------------------------------------------------------------------
__global__ void split_k(const float* __restrict__ src,
                        __nv_bfloat16* __restrict__ hi,
                        __nv_bfloat16* __restrict__ lo, int n4) {
    int i = blockIdx.x * blockDim.x + threadIdx.x;
    if (i >= n4) return;
    float4 f = ((const float4*)src)[i];
    __nv_bfloat16 h0 = __float2bfloat16(f.x);
    __nv_bfloat16 h1 = __float2bfloat16(f.y);
    __nv_bfloat16 h2 = __float2bfloat16(f.z);
    __nv_bfloat16 h3 = __float2bfloat16(f.w);
    __nv_bfloat162 hv0, hv1, lv0, lv1;
    hv0.x = h0; hv0.y = h1; hv1.x = h2; hv1.y = h3;
    lv0.x = __float2bfloat16(f.x - __bfloat162float(h0));
    lv0.y = __float2bfloat16(f.y - __bfloat162float(h1));
    lv1.x = __float2bfloat16(f.z - __bfloat162float(h2));
    lv1.y = __float2bfloat16(f.w - __bfloat162float(h3));
    ((__nv_bfloat162*)hi)[2 * i]     = hv0;
    ((__nv_bfloat162*)hi)[2 * i + 1] = hv1;
    ((__nv_bfloat162*)lo)[2 * i]     = lv0;
    ((__nv_bfloat162*)lo)[2 * i + 1] = lv1;
}

// ---------------------------------------------------------------------------
__device__ __forceinline__ void ldsm_x4(uint32_t& r0, uint32_t& r1,
                                        uint32_t& r2, uint32_t& r3, uint32_t a) {
    asm volatile("ldmatrix.sync.aligned.m8n8.x4.shared.b16 {%0,%1,%2,%3}, [%4];"
                 : "=r"(r0), "=r"(r1), "=r"(r2), "=r"(r3) : "r"(a));
}
__device__ __forceinline__ void ldsm_x2(uint32_t& r0, uint32_t& r1, uint32_t a) {
    asm volatile("ldmatrix.sync.aligned.m8n8.x2.shared.b16 {%0,%1}, [%2];"
                 : "=r"(r0), "=r"(r1) : "r"(a));
}
__device__ __forceinline__ void mma16816(float* c, const uint32_t* a,
                                         uint32_t b0, uint32_t b1) {
    asm volatile(
        "mma.sync.aligned.m16n8k16.row.col.f32.bf16.bf16.f32 "
        "{%0,%1,%2,%3},{%4,%5,%6,%7},{%8,%9},{%0,%1,%2,%3};"
        : "+f"(c[0]), "+f"(c[1]), "+f"(c[2]), "+f"(c[3])
        : "r"(a[0]), "r"(a[1]), "r"(a[2]), "r"(a[3]), "r"(b0), "r"(b1));
}
__device__ __forceinline__ void cpa16(uint32_t dst, const void* src) {
    asm volatile("cp.async.cg.shared.global [%0], [%1], 16;"
                 :: "r"(dst), "l"(src));
}
__device__ __forceinline__ void cpa_commit() {
    asm volatile("cp.async.commit_group;");
}

// ---------------------------------------------------------------------------
// Tensor-core input GEMM — k-tile 32, 2-stage cp.async pipeline (16 syncs).
// Compute phase processes the two k16 halves sequentially with the same
// fragment registers, so register pressure matches the k16 version.
// ---------------------------------------------------------------------------
#define ASTR2  80
#define STAGE2 (4 * 128 * ASTR2)   // 40960 B per stage

__global__ __launch_bounds__(256, 2) void gemm_pi_mma_k(const float* __restrict__ bi) {
    extern __shared__ char smg[];

    const int tid  = threadIdx.x;
    const int lane = tid & 31;
    const int warp = tid >> 5;
    const int wm   = warp >> 2;
    const int wn   = warp & 3;
    const int m0   = blockIdx.y * 128;
    const int n0   = blockIdx.x * 128;

    const int lrow  = tid >> 1;
    const int lhalf = tid & 1;           // which 32B (16-elem) half of the 64B row
    const __nv_bfloat16* pxh = g_xhi + (size_t)(m0 + lrow) * D_;
    const __nv_bfloat16* pxl = g_xlo + (size_t)(m0 + lrow) * D_;
    const __nv_bfloat16* pwh = g_whi + (size_t)(n0 + lrow) * D_;
    const __nv_bfloat16* pwl = g_wlo + (size_t)(n0 + lrow) * D_;

    const uint32_t sbase = (uint32_t)__cvta_generic_to_shared(smg);
    const uint32_t stoff = lrow * ASTR2 + lhalf * 32;

    const int rowA = wm * 64 + (lane & 15);
    const uint32_t aAh0 = sbase + rowA * ASTR2 + (lane >> 4) * 16;
    const uint32_t aAl0 = aAh0 + 128 * ASTR2;
    const int rowB = wn * 32 + (lane & 7) + ((lane >> 4) << 3);
    const uint32_t aBh0 = sbase + 2 * 128 * ASTR2 + rowB * ASTR2 + ((lane >> 3) & 1) * 16;
    const uint32_t aBl0 = aBh0 + 128 * ASTR2;

    float acc[4][4][4];
#pragma unroll
    for (int i = 0; i < 4; i++)
#pragma unroll
        for (int j = 0; j < 4; j++)
#pragma unroll
            for (int e = 0; e < 4; e++) acc[i][j][e] = 0.f;

    auto commit_stage = [&](int p, int kts) {
        uint32_t d = sbase + p * STAGE2 + stoff;
        const int ko = kts * 32 + lhalf * 16;
        cpa16(d,                        pxh + ko);
        cpa16(d + 16,                   pxh + ko + 8);
        cpa16(d +     128 * ASTR2,      pxl + ko);
        cpa16(d +     128 * ASTR2 + 16, pxl + ko + 8);
        cpa16(d + 2 * 128 * ASTR2,      pwh + ko);
        cpa16(d + 2 * 128 * ASTR2 + 16, pwh + ko + 8);
        cpa16(d + 3 * 128 * ASTR2,      pwl + ko);
        cpa16(d + 3 * 128 * ASTR2 + 16, pwl + ko + 8);
        cpa_commit();
    };

    commit_stage(0, 0);

    for (int kts = 0; kts < 16; kts++) {
        asm volatile("cp.async.wait_group 0;");
        __syncthreads();
        if (kts + 1 < 16) commit_stage((kts + 1) & 1, kts + 1);

        const uint32_t po = (kts & 1) * STAGE2;

#pragma unroll
        for (int kk = 0; kk < 2; kk++) {
            const uint32_t kko = po + kk * 32;
            uint32_t ah[4][4], al[4][4], bh[4][2], bl[4][2];
#pragma unroll
            for (int mi = 0; mi < 4; mi++) {
                ldsm_x4(ah[mi][0], ah[mi][1], ah[mi][2], ah[mi][3],
                        aAh0 + kko + mi * 16 * ASTR2);
                ldsm_x4(al[mi][0], al[mi][1], al[mi][2], al[mi][3],
                        aAl0 + kko + mi * 16 * ASTR2);
            }
#pragma unroll
            for (int bg = 0; bg < 2; bg++) {
                ldsm_x4(bh[2 * bg][0], bh[2 * bg][1], bh[2 * bg + 1][0], bh[2 * bg + 1][1],
                        aBh0 + kko + bg * 16 * ASTR2);
                ldsm_x4(bl[2 * bg][0], bl[2 * bg][1], bl[2 * bg + 1][0], bl[2 * bg + 1][1],
                        aBl0 + kko + bg * 16 * ASTR2);
            }
#pragma unroll
            for (int mi = 0; mi < 4; mi++)
#pragma unroll
                for (int ni = 0; ni < 4; ni++) {
                    mma16816(acc[mi][ni], ah[mi], bh[ni][0], bh[ni][1]);
                    mma16816(acc[mi][ni], ah[mi], bl[ni][0], bl[ni][1]);
                    mma16816(acc[mi][ni], al[mi], bh[ni][0], bh[ni][1]);
                }
        }
    }

#pragma unroll
    for (int ni = 0; ni < 4; ni++) {
        const int n = n0 + wn * 32 + ni * 8 + 2 * (lane & 3);
        float b0 = bi[n], b1 = bi[n + 1];
#pragma unroll
        for (int mi = 0; mi < 4; mi++) {
            const int m = m0 + wm * 64 + mi * 16 + (lane >> 2);
            float* C0 = g_pi + (size_t)m * SIXH + n;
            float* C1 = g_pi + (size_t)(m + 8) * SIXH + n;
            *(float2*)C0 = make_float2(acc[mi][ni][0] + b0, acc[mi][ni][1] + b1);
            *(float2*)C1 = make_float2(acc[mi][ni][2] + b0, acc[mi][ni][3] + b1);
        }
    }
}

// ---------------------------------------------------------------------------
// Persistent scan — EXACT Round-6 structure (the validated 2153.6us config):
// per-k-chunk dataflow sync with threadfence + atomicAdd + volatile poll.
// ---------------------------------------------------------------------------
__device__ __forceinline__ float sigm(float x)  { return 1.f / (1.f + __expf(-x)); }
__device__ __forceinline__ float tanh_(float x) { return 1.f - 2.f / (__expf(2.f * x) + 1.f); }

__global__ __launch_bounds__(NTHR, 1) void lstm_scan_k(
    const float* __restrict__ Ws, const float* __restrict__ bs,
    const int* __restrict__ lengths, float* __restrict__ out)
{
    extern __shared__ char smc[];
    __nv_bfloat16* sAh   = (__nv_bfloat16*)smc;          // 16 x SSTR
    __nv_bfloat16* sAl   = sAh + 16 * SSTR;              // 16 x SSTR
    __nv_bfloat16* sWh   = sAl + 16 * SSTR;              // NROW x SSTR
    __nv_bfloat16* sWl   = sWh + NROW * SSTR;            // NROW x SSTR
    float*         sPart = (float*)(sWl + NROW * SSTR);  // 8 x 16 x PSTR

    const int tid   = threadIdx.x;
    const int blk   = blockIdx.x;
    const int lane  = tid & 31;
    const int warp  = tid >> 5;
    const int group = blk >> 6;
    const int cb    = blk & 63;
    const int sub   = cb >> 3;
    const int kh    = warp;           // k-chunk owned by this warp

    // --- Ws -> smem bf16 split ---
    for (int i = tid; i < NROW * (H_ / 8); i += NTHR) {
        int l  = i >> 6;
        int d8 = (i & 63) << 3;
        __nv_bfloat16* ph = sWh + l * SSTR + d8;
        __nv_bfloat16* pl = sWl + l * SSTR + d8;
        int row = (l >> 3) * H_ + cb * CPB + (l & 7);
        const float* p = Ws + (size_t)row * H_ + d8;
#pragma unroll
        for (int q = 0; q < 8; q++) {
            float f = p[q];
            __nv_bfloat16 hh = __float2bfloat16(f);
            ph[q] = hh;
            pl[q] = __float2bfloat16(f - __bfloat162float(hh));
        }
    }

    // MMA addressing: warp = k-chunk kh (64 k-elems each)
    const uint32_t aAh = (uint32_t)__cvta_generic_to_shared(
        sAh + (size_t)(lane & 15) * SSTR) + (lane >> 4) * 16 + kh * 128;
    const uint32_t aAl = aAh + 16 * SSTR * 2;
    const uint32_t aBh = (uint32_t)__cvta_generic_to_shared(
        sWh + (size_t)(lane & 7) * SSTR) + ((lane >> 3) & 1) * 16 + kh * 128;
    const uint32_t aBl = aBh + NROW * SSTR * 2;

    // Gate threads: tid<128 owns (b_local = tid>>3, jj = tid&7)
    float c_reg = 0.f, h_reg = 0.f;
    float bsv[5] = {0.f, 0.f, 0.f, 0.f, 0.f};
    int bg = 0, j0 = 0, len = 0, b_local = 0;
    if (tid < 128) {
        b_local = tid >> 3;
        bg = group * BGRP + b_local;
        j0 = cb * CPB + (tid & 7);
        len = lengths[bg];
#pragma unroll
        for (int g = 0; g < 5; g++) bsv[g] = bs[g * H_ + j0];
        __stcg((unsigned short*)&g_hhi[bg * H_ + j0], (unsigned short)0);
        __stcg((unsigned short*)&g_hlo[bg * H_ + j0], (unsigned short)0);
        __threadfence();
    }
    __syncthreads();
    if (tid == 0) atomicAdd(&g_cnt[group][sub], 1u);   // h0 published

    const int hbase = group * BGRP * H_;
    const volatile unsigned* cptr = &g_cnt[group][kh];
    const uint32_t dh = (uint32_t)__cvta_generic_to_shared(sAh);
    const uint32_t dl = (uint32_t)__cvta_generic_to_shared(sAl);

    // Deep pi prefetch
    float pv_cur[6] = {0,0,0,0,0,0}, pv_nxt[6] = {0,0,0,0,0,0};
    const float* ppi = (tid < 128) ? g_pi + (size_t)bg * T_ * SIXH + j0 : g_pi;
    if (tid < 128) {
#pragma unroll
        for (int g = 0; g < 6; g++) pv_cur[g] = __ldg(ppi + g * H_);
    }

    for (int t = 0; t < T_; t++) {
        // next step's pi loads (overlap the poll)
        if (tid < 128 && t + 1 < T_) {
            const float* pp = ppi + (size_t)(t + 1) * SIXH;
#pragma unroll
            for (int g = 0; g < 6; g++) pv_nxt[g] = __ldg(pp + g * H_);
        }

        // poll my chunk's writers (subgroup kh of my group)
        if (lane == 0) {
            while (*cptr < 8u * (unsigned)(t + 1)) {}
        }
        __syncwarp();

        // warp-local copy of chunk kh: 16 rows x 64 cols, hi+lo
        {
            const char* ph = (const char*)(g_hhi + (t & 1) * BH + hbase);
            const char* pl = (const char*)(g_hlo + (t & 1) * BH + hbase);
#pragma unroll
            for (int i = lane; i < 128; i += 32) {
                int r  = i >> 3;
                int cc = ((i & 7) << 3) + kh * 64;
                cpa16(dh + (r * SSTR + cc) * 2, ph + (r * H_ + cc) * 2);
                cpa16(dl + (r * SSTR + cc) * 2, pl + (r * H_ + cc) * 2);
            }
            cpa_commit();
            asm volatile("cp.async.wait_group 0;");
            __syncwarp();
        }

        // MMA: 16x40 partial over k-chunk [kh*64, kh*64+64)
        {
            float acc[5][4];
#pragma unroll
            for (int ni = 0; ni < 5; ni++)
#pragma unroll
                for (int e = 0; e < 4; e++) acc[ni][e] = 0.f;
#pragma unroll
            for (int kk = 0; kk < 4; kk++) {
                const uint32_t ko = kk * 32;
                uint32_t Ah[4], Al[4];
                ldsm_x4(Ah[0], Ah[1], Ah[2], Ah[3], aAh + ko);
                ldsm_x4(Al[0], Al[1], Al[2], Al[3], aAl + ko);
#pragma unroll
                for (int ni = 0; ni < 5; ni++) {
                    const uint32_t bo = ko + ni * 8 * SSTR * 2;
                    uint32_t b0h, b1h, b0l, b1l;
                    ldsm_x2(b0h, b1h, aBh + bo);
                    ldsm_x2(b0l, b1l, aBl + bo);
                    mma16816(acc[ni], Ah, b0h, b1h);
                    mma16816(acc[ni], Al, b0h, b1h);
                    mma16816(acc[ni], Ah, b0l, b1l);
                }
            }
            float* pp = sPart + kh * 16 * PSTR;
            const int r = lane >> 2;
#pragma unroll
            for (int ni = 0; ni < 5; ni++) {
                const int n = ni * 8 + 2 * (lane & 3);
                *(float2*)&pp[r * PSTR + n]       = make_float2(acc[ni][0], acc[ni][1]);
                *(float2*)&pp[(r + 8) * PSTR + n] = make_float2(acc[ni][2], acc[ni][3]);
            }
        }
        __syncthreads();   // partials ready

        // Gate phase
        if (tid < 128) {
            const int jj = tid & 7;
            float ps[5];
#pragma unroll
            for (int g = 0; g < 5; g++) {
                float s = 0.f;
#pragma unroll
                for (int w = 0; w < 8; w++)
                    s += sPart[w * 16 * PSTR + b_local * PSTR + g * 8 + jj];
                ps[g] = s + bsv[g];
            }
            float iv = sigm(pv_cur[0] + ps[0]);
            float fv = sigm(pv_cur[1] + ps[1]);
            float gv = tanh_(pv_cur[2] + ps[2]);
            float ov = sigm(pv_cur[3] + ps[3]);
            float cn = iv * gv + fv * c_reg;
            float o1 = ov * tanh_(cn);
            float rv = sigm(pv_cur[4] + ps[4]);
            float o2 = rv * o1 + (1.f - rv) * pv_cur[5];
            bool  m  = (t < len);
            h_reg = m ? o2 : h_reg;
            c_reg = m ? cn : c_reg;
            __nv_bfloat16 hh = __float2bfloat16(h_reg);
            __nv_bfloat16 hl = __float2bfloat16(h_reg - __bfloat162float(hh));
            const int idx = ((t + 1) & 1) * BH + bg * H_ + j0;
            __stcg((unsigned short*)&g_hhi[idx], __bfloat16_as_ushort(hh));
            __stcg((unsigned short*)&g_hlo[idx], __bfloat16_as_ushort(hl));
            out[((size_t)bg * T_ + t) * H_ + j0] = m ? o2 : 0.f;
            if (t == T_ - 1) {
                out[(size_t)B_ * T_ * H_ + bg * H_ + j0]      = h_reg;
                out[(size_t)B_ * T_ * H_ + BH + bg * H_ + j0] = c_reg;
            }
            __threadfence();   // publish h before arrival
        }
#pragma unroll
        for (int g = 0; g < 6; g++) pv_cur[g] = pv_nxt[g];

        __syncthreads();       // gates done, sPart consumable, h published
        if (tid == 0) atomicAdd(&g_cnt[group][sub], 1u);
    }
}

// ---------------------------------------------------------------------------
extern "C" void kernel_launch(void* const* d_in, const int* in_sizes, int n_in,
                              void* d_out, int out_size) {
    const float* x       = (const float*)d_in[0];
    const int*   lengths = (const int*)  d_in[1];
    const float* Wi      = (const float*)d_in[2];
    const float* bi      = (const float*)d_in[3];
    const float* Ws      = (const float*)d_in[4];
    const float* bs      = (const float*)d_in[5];
    float* out = (float*)d_out;

    const int smem_scan = (16 + 16 + NROW + NROW) * SSTR * 2 + 8 * 16 * PSTR * 4; // 139,008 B
    const int smem_gemm = 2 * STAGE2;                                             // 81,920 B
    cudaFuncSetAttribute(lstm_scan_k,   cudaFuncAttributeMaxDynamicSharedMemorySize, smem_scan);
    cudaFuncSetAttribute(gemm_pi_mma_k, cudaFuncAttributeMaxDynamicSharedMemorySize, smem_gemm);

    init_k<<<1, 1>>>();

    __nv_bfloat16 *xhi, *xlo, *whi, *wlo;
    cudaGetSymbolAddress((void**)&xhi, g_xhi);
    cudaGetSymbolAddress((void**)&xlo, g_xlo);
    cudaGetSymbolAddress((void**)&whi, g_whi);
    cudaGetSymbolAddress((void**)&wlo, g_wlo);

    int nx4 = (B_ * T_ * D_) / 4;
    int nw4 = (SIXH * D_) / 4;
    split_k<<<(nx4 + 255) / 256, 256>>>(x, xhi, xlo, nx4);
    split_k<<<(nw4 + 255) / 256, 256>>>(Wi, whi, wlo, nw4);

    gemm_pi_mma_k<<<dim3(SIXH / 128, (B_ * T_) / 128), 256, smem_gemm>>>(bi);
    lstm_scan_k<<<NBLK, NTHR, smem_scan>>>(Ws, bs, lengths, out);
}